// round 14
// baseline (speedup 1.0000x reference)
#include <cuda_runtime.h>
#include <cuda_bf16.h>
#include <cuda_fp8.h>
#include <cstdint>

// ---------------- Problem constants ----------------
#define TT 4
#define BB 16
#define CC 512
#define NN 256
#define NHEAD 8
#define DH 64
#define HID 2048
#define MROWS (TT*BB*NN)  // 16384
#define BNROWS (BB*NN)    // 4096
#define PLANE (BB*CC*NN)  // 2097152

// Row ordering for token-major tensors: r = bn*4 + t

// ---------------- Static device scratch ----------------
__device__ float          g_xt [(size_t)MROWS*CC];
__device__ float          g_y  [(size_t)TT*PLANE];
__device__ float          g_kv [(size_t)TT*BB*NHEAD*DH*DH];
__device__ unsigned char  g_h  [(size_t)MROWS*CC];    // e4m3 spikes
__device__ unsigned char  g_h4 [(size_t)MROWS*HID];   // e4m3 spikes
__device__ uint32_t       g_qm [(size_t)TT*BB*NHEAD*NN*2];
__device__ uint32_t       g_km [(size_t)TT*BB*NHEAD*NN*2];
__device__ uint32_t       g_vm [(size_t)TT*BB*NHEAD*NN*2];
__device__ unsigned char  g_wq [(size_t)3*CC*CC];     // e4m3 weights
__device__ unsigned char  g_wp [(size_t)CC*CC];
__device__ unsigned char  g_w1 [(size_t)HID*CC];
__device__ unsigned char  g_w2 [(size_t)CC*HID];
// per-128-row-block nonzero flags for GEMM LHS skip
__device__ uint32_t       g_fh1[128];
__device__ uint32_t       g_fha[128];
__device__ uint32_t       g_fh3[128];
__device__ uint32_t       g_f4 [128];

__device__ __forceinline__ float sigmoidf_(float w){ return 1.f/(1.f+expf(-w)); }
__device__ __forceinline__ uint32_t smem_u32(const void* p){
    uint32_t a;
    asm("{ .reg .u64 t; cvta.to.shared.u64 t, %1; cvt.u32.u64 %0, t; }" : "=r"(a) : "l"(p));
    return a;
}
__device__ __forceinline__ uint32_t f2e4(float f){
    return (uint32_t)__nv_cvt_float_to_fp8(f, __NV_SATFINITE, __NV_E4M3);
}
#define FP8_ONE 0x38u

// ---------------- all weights -> e4m3 (+flag clear), one kernel ----------------
__global__ void k_cvt_all(const float* __restrict__ a0, const float* __restrict__ a1,
                          const float* __restrict__ a2, const float* __restrict__ a3,
                          uint8_t* __restrict__ d0, uint8_t* __restrict__ d1,
                          uint8_t* __restrict__ d2, uint8_t* __restrict__ d3,
                          uint32_t* f1, uint32_t* f2, uint32_t* f3, uint32_t* f4){
    if (blockIdx.x == 0 && threadIdx.x < 128){
        int i = threadIdx.x;
        f1[i] = 0; f2[i] = 0; f3[i] = 0; f4[i] = 0;
    }
    int i = blockIdx.x*blockDim.x + threadIdx.x;   // float4 index
    const int n0 = 196608, n1 = 65536, n2 = 262144, n3 = 262144;
    const float* s; uint8_t* d; int off;
    if      (i < n0){            s=a0; d=d0; off=i; }
    else if (i < n0+n1){         s=a1; d=d1; off=i-n0; }
    else if (i < n0+n1+n2){      s=a2; d=d2; off=i-n0-n1; }
    else if (i < n0+n1+n2+n3){   s=a3; d=d3; off=i-n0-n1-n2; }
    else return;
    float4 v = ((const float4*)s)[off];
    uint32_t w = f2e4(v.x) | (f2e4(v.y)<<8) | (f2e4(v.z)<<16) | (f2e4(v.w)<<24);
    ((uint32_t*)d)[off] = w;
}

// ---------------- fused LIF(x) + depthwise 3x3 conv + residual ----------------
__global__ void __launch_bounds__(256) k_lifconv(
        const float* __restrict__ x, const float* __restrict__ lw,
        const float* __restrict__ cw, const float* __restrict__ cb,
        float* __restrict__ y){
    __shared__ unsigned char sp[4][256];
    int b = blockIdx.x >> 9, c = blockIdx.x & 511;
    int px = threadIdx.x;
    size_t base = ((size_t)b*512 + c)*256 + px;
    float decay = sigmoidf_(lw[0]);
    float xv[4];
#pragma unroll
    for (int t = 0; t < 4; t++) xv[t] = x[(size_t)t*PLANE + base];
    float v = 0.f;
#pragma unroll
    for (int t = 0; t < 4; t++){
        v += (xv[t] - v)*decay;
        unsigned char s = (v >= 1.f);
        sp[t][px] = s;
        if (s) v = 0.f;
    }
    __syncthreads();
    float wk[9];
#pragma unroll
    for (int j = 0; j < 9; j++) wk[j] = cw[c*9 + j];
    float bias = cb[c];
    int h = px >> 4, w = px & 15;
#pragma unroll
    for (int t = 0; t < 4; t++){
        float acc = bias;
#pragma unroll
        for (int dy = -1; dy <= 1; dy++){
            int hh = h + dy; if ((unsigned)hh >= 16u) continue;
#pragma unroll
            for (int dx = -1; dx <= 1; dx++){
                int ww = w + dx; if ((unsigned)ww >= 16u) continue;
                acc += wk[(dy+1)*3 + (dx+1)] * (float)sp[t][hh*16 + ww];
            }
        }
        y[(size_t)t*PLANE + base] = xv[t] + acc;
    }
}

// ---------------- transpose [tb][C][N] -> xt rows (bn*4+t) ----------------
__global__ void __launch_bounds__(256) k_tr(const float* __restrict__ y, float* __restrict__ xt){
    __shared__ float s[64][65];
    int bz = blockIdx.z;                 // t*16+b
    int t = bz >> 4, b = bz & 15;
    int n0 = blockIdx.x*64, c0 = blockIdx.y*64;
    int tid = threadIdx.x;
    const float* src = y + (size_t)bz*512*256;
#pragma unroll
    for (int it = 0; it < 4; it++){
        int cr = it*16 + (tid >> 4), ng = (tid & 15)*4;
        float4 f = *(const float4*)&src[(size_t)(c0+cr)*256 + n0 + ng];
        s[cr][ng+0] = f.x; s[cr][ng+1] = f.y; s[cr][ng+2] = f.z; s[cr][ng+3] = f.w;
    }
    __syncthreads();
#pragma unroll
    for (int it = 0; it < 4; it++){
        int nr = it*16 + (tid >> 4), cg = (tid & 15)*4;
        size_t row = (size_t)(b*256 + n0 + nr)*4 + t;
        float4 f = make_float4(s[cg][nr], s[cg+1][nr], s[cg+2][nr], s[cg+3][nr]);
        *(float4*)&xt[row*512 + c0 + cg] = f;
    }
}

// ---------------- LayerNorm(C) + LIF over T -> e4m3 spikes (+flags), 1 sync ----------------
__global__ void __launch_bounds__(128) k_ln_lif(
        const float* __restrict__ xt, const float* __restrict__ g, const float* __restrict__ bv,
        const float* __restrict__ lw, int lwi, uint8_t* __restrict__ h,
        uint32_t* __restrict__ flag){
    int bn = blockIdx.x, tid = threadIdx.x;
    int lane = tid & 31, w = tid >> 5;
    __shared__ float sred[4][8];         // [warp][4 sums + 4 sumsq]
    float decay = sigmoidf_(lw[lwi]);
    float4 gg = *(const float4*)&g[tid*4];
    float4 bb = *(const float4*)&bv[tid*4];
    float4 xv[4];
    float sm[4], sq[4];
#pragma unroll
    for (int t = 0; t < 4; t++){
        xv[t] = *(const float4*)&xt[((size_t)bn*4 + t)*512 + tid*4];
        sm[t] = xv[t].x + xv[t].y + xv[t].z + xv[t].w;
        sq[t] = xv[t].x*xv[t].x + xv[t].y*xv[t].y + xv[t].z*xv[t].z + xv[t].w*xv[t].w;
    }
#pragma unroll
    for (int o = 16; o > 0; o >>= 1){
#pragma unroll
        for (int t = 0; t < 4; t++){
            sm[t] += __shfl_xor_sync(0xffffffffu, sm[t], o);
            sq[t] += __shfl_xor_sync(0xffffffffu, sq[t], o);
        }
    }
    if (lane < 8) sred[w][lane] = (lane < 4) ? sm[lane] : sq[lane-4];
    __syncthreads();
    float v0=0,v1=0,v2=0,v3=0;
    bool any = false;
#pragma unroll
    for (int t = 0; t < 4; t++){
        float ts = sred[0][t] + sred[1][t] + sred[2][t] + sred[3][t];
        float tq = sred[0][t+4] + sred[1][t+4] + sred[2][t+4] + sred[3][t+4];
        float mean = ts*(1.f/512.f);
        float var  = tq*(1.f/512.f) - mean*mean;
        float rstd = rsqrtf(var + 1e-5f);
        float4 xw = xv[t];
        float y0 = (xw.x-mean)*rstd*gg.x + bb.x;
        float y1 = (xw.y-mean)*rstd*gg.y + bb.y;
        float y2 = (xw.z-mean)*rstd*gg.z + bb.z;
        float y3 = (xw.w-mean)*rstd*gg.w + bb.w;
        v0 += (y0-v0)*decay; v1 += (y1-v1)*decay; v2 += (y2-v2)*decay; v3 += (y3-v3)*decay;
        bool s0 = v0>=1.f, s1 = v1>=1.f, s2 = v2>=1.f, s3 = v3>=1.f;
        any |= (s0|s1|s2|s3);
        uint32_t pw = (s0?FP8_ONE:0u) | ((s1?FP8_ONE:0u)<<8)
                    | ((s2?FP8_ONE:0u)<<16) | ((s3?FP8_ONE:0u)<<24);
        ((uint32_t*)(h + ((size_t)bn*4 + t)*512))[tid] = pw;
        if (s0) v0=0.f; if (s1) v1=0.f; if (s2) v2=0.f; if (s3) v3=0.f;
    }
    uint32_t m = __ballot_sync(0xffffffffu, any);
    if (lane == 0 && m) atomicOr(&flag[bn >> 5], 1u);
}

// ---------------- FP8 GEMM, tile 128x64, 3-stage ring, 4 CTAs/SM ----------------
#define BMT 128
#define BNT 64
#define BKB 64
#define STG 3
#define ROWB 80
#define STAGE_BYTES ((BMT+BNT)*ROWB)    // 15360
#define GEMM_DSMEM (STG*STAGE_BYTES)    // 46080

template<int EP, int K>
__global__ void __launch_bounds__(256, 4) k_gemm(
        const uint8_t* __restrict__ A, const uint8_t* __restrict__ W,
        int N,
        const float* __restrict__ lw, const float* __restrict__ bias,
        float* __restrict__ xt, float* __restrict__ out,
        uint32_t* __restrict__ qm, uint32_t* __restrict__ km, uint32_t* __restrict__ vm,
        uint8_t* __restrict__ h4,
        const uint32_t* __restrict__ nzf, uint32_t* __restrict__ outflag){
    extern __shared__ char dsm[];
    const int tid  = threadIdx.x;
    const int lane = tid & 31, warp = tid >> 5;
    const int wm = warp >> 1, wn = warp & 1;      // 4m x 2n warps; warp tile 32x32
    const int bm = blockIdx.y*BMT, bn = blockIdx.x*BNT;
    const uint32_t sbase = smem_u32(dsm);
    constexpr int nk = K >> 6;

    float acc[2][4][4];
#pragma unroll
    for (int i = 0; i < 2; i++)
#pragma unroll
        for (int j = 0; j < 4; j++)
#pragma unroll
            for (int r = 0; r < 4; r++) acc[i][j][r] = 0.f;

    const bool live = (nzf == nullptr) || (nzf[blockIdx.y] != 0);

    if (live){
        // hoisted per-thread copy addressing
        const int crow = tid >> 2, ccol = (tid & 3)*16;
        const uint8_t* gA0 = A + (size_t)(bm + crow)*K + ccol;
        const uint8_t* gA1 = gA0 + (size_t)64*K;
        const uint8_t* gB  = W + (size_t)(bn + crow)*K + ccol;
        const uint32_t dA0 = sbase + (uint32_t)(crow*ROWB + ccol);
        const uint32_t dA1 = dA0 + 64*ROWB;
        const uint32_t dB  = sbase + (uint32_t)(BMT*ROWB + crow*ROWB + ccol);

        auto load_stage = [&](int j, uint32_t so){
            const uint8_t* p0 = gA0 + j*BKB;
            const uint8_t* p1 = gA1 + j*BKB;
            const uint8_t* pb = gB  + j*BKB;
            asm volatile("cp.async.cg.shared.global [%0], [%1], 16;" :: "r"(dA0+so), "l"(p0));
            asm volatile("cp.async.cg.shared.global [%0], [%1], 16;" :: "r"(dA1+so), "l"(p1));
            asm volatile("cp.async.cg.shared.global [%0], [%1], 16;" :: "r"(dB +so), "l"(pb));
            asm volatile("cp.async.commit_group;");
        };

        // hoisted fragment smem offsets
        uint32_t aoff[2], boff[2];
#pragma unroll
        for (int mt = 0; mt < 2; mt++)
            aoff[mt] = (uint32_t)((wm*32 + mt*16 + (lane & 15))*ROWB + ((lane >> 4) << 4));
#pragma unroll
        for (int ng = 0; ng < 2; ng++)
            boff[ng] = (uint32_t)(BMT*ROWB +
                       (wn*32 + ng*16 + (lane & 7) + (((lane >> 4) & 1) << 3))*ROWB +
                       (((lane >> 3) & 1) << 4));

        load_stage(0, 0);
        load_stage(1, STAGE_BYTES);

        uint32_t so_c = 0;                       // compute-stage offset
        uint32_t so_l = 2*STAGE_BYTES;           // load-target offset (j+2)
#pragma unroll 3
        for (int j = 0; j < nk; j++){
            asm volatile("cp.async.wait_group 1;");
            __syncthreads();
            uint32_t so = sbase + so_c;
#pragma unroll
            for (int ks = 0; ks < 2; ks++){
                uint32_t a[2][4], b[2][4];
#pragma unroll
                for (int mt = 0; mt < 2; mt++){
                    uint32_t ad = so + aoff[mt] + ks*32;
                    asm volatile("ldmatrix.sync.aligned.m8n8.x4.shared.b16 {%0,%1,%2,%3}, [%4];"
                                 : "=r"(a[mt][0]), "=r"(a[mt][1]), "=r"(a[mt][2]), "=r"(a[mt][3])
                                 : "r"(ad));
                }
#pragma unroll
                for (int ng = 0; ng < 2; ng++){
                    uint32_t bd = so + boff[ng] + ks*32;
                    asm volatile("ldmatrix.sync.aligned.m8n8.x4.shared.b16 {%0,%1,%2,%3}, [%4];"
                                 : "=r"(b[ng][0]), "=r"(b[ng][1]), "=r"(b[ng][2]), "=r"(b[ng][3])
                                 : "r"(bd));
                }
#pragma unroll
                for (int mt = 0; mt < 2; mt++)
#pragma unroll
                    for (int nf = 0; nf < 4; nf++){
                        uint32_t b0 = b[nf >> 1][(nf & 1)*2];
                        uint32_t b1 = b[nf >> 1][(nf & 1)*2 + 1];
                        asm volatile(
                            "mma.sync.aligned.m16n8k32.row.col.f32.e4m3.e4m3.f32 "
                            "{%0,%1,%2,%3}, {%4,%5,%6,%7}, {%8,%9}, {%0,%1,%2,%3};"
                            : "+f"(acc[mt][nf][0]), "+f"(acc[mt][nf][1]),
                              "+f"(acc[mt][nf][2]), "+f"(acc[mt][nf][3])
                            : "r"(a[mt][0]), "r"(a[mt][1]), "r"(a[mt][2]), "r"(a[mt][3]),
                              "r"(b0), "r"(b1));
                    }
            }
            if (j + 2 < nk) load_stage(j + 2, so_l);
            else            asm volatile("cp.async.commit_group;");
            so_c = (so_c == 2*STAGE_BYTES) ? 0u : so_c + STAGE_BYTES;
            so_l = (so_l == 2*STAGE_BYTES) ? 0u : so_l + STAGE_BYTES;
        }
        asm volatile("cp.async.wait_group 0;");
    }

    // ================= epilogues =================
    if (EP == 1){
#pragma unroll
        for (int mt = 0; mt < 2; mt++){
            int r0 = bm + wm*32 + mt*16 + (lane >> 2);
#pragma unroll
            for (int nf = 0; nf < 4; nf++){
                int col = bn + wn*32 + nf*8 + (lane & 3)*2;
                float2 bb = *(const float2*)&bias[col];
                float2* p0 = (float2*)&xt[(size_t)r0*512 + col];
                float2 q0 = *p0;
                q0.x += acc[mt][nf][0] + bb.x; q0.y += acc[mt][nf][1] + bb.y;
                *p0 = q0;
                float2* p1 = (float2*)&xt[(size_t)(r0+8)*512 + col];
                float2 q1 = *p1;
                q1.x += acc[mt][nf][2] + bb.x; q1.y += acc[mt][nf][3] + bb.y;
                *p1 = q1;
            }
        }
        return;
    }

    if (EP == 3){
#pragma unroll
        for (int mt = 0; mt < 2; mt++){
            int r0 = bm + wm*32 + mt*16 + (lane >> 2);
#pragma unroll
            for (int nf = 0; nf < 4; nf++){
                int col = bn + wn*32 + nf*8 + (lane & 3)*2;
                float2 bb = *(const float2*)&bias[col];
                float2 x0 = *(const float2*)&xt[(size_t)r0*512 + col];
                float2 x1 = *(const float2*)&xt[(size_t)(r0+8)*512 + col];
                acc[mt][nf][0] += x0.x + bb.x; acc[mt][nf][1] += x0.y + bb.y;
                acc[mt][nf][2] += x1.x + bb.x; acc[mt][nf][3] += x1.y + bb.y;
            }
        }
    }

    // chunked smem epilogue (EP 0, 2, 3): 2 chunks of 32 cols
    bool anyep2 = false;
    float* es = (float*)dsm;
    for (int cc = 0; cc < 2; cc++){
        __syncthreads();
        if (wn == cc){
#pragma unroll
            for (int mt = 0; mt < 2; mt++)
#pragma unroll
                for (int f = 0; f < 4; f++){
                    int lc = f*8 + (lane & 3)*2;
                    int r0 = wm*32 + mt*16 + (lane >> 2);
                    es[r0*33 + lc]     = acc[mt][f][0];
                    es[r0*33 + lc + 1] = acc[mt][f][1];
                    es[(r0+8)*33 + lc]     = acc[mt][f][2];
                    es[(r0+8)*33 + lc + 1] = acc[mt][f][3];
                }
        }
        __syncthreads();
        int col0 = bn + cc*32;
        if (EP == 0){
            int isel = col0 >> 9, hh = (col0 >> 6) & 7, gsel = (col0 >> 5) & 1;
            float decay = sigmoidf_(lw[2 + isel]);
            uint32_t* mdst = (isel == 0) ? qm : (isel == 1) ? km : vm;
#pragma unroll
            for (int k2 = 0; k2 < 4; k2++){
                int j = k2*8 + warp;
                int tok = (bm >> 2) + j;
                int b = tok >> 8, n = tok & 255;
                float v = 0.f;
#pragma unroll
                for (int t = 0; t < 4; t++){
                    float val = es[(4*j + t)*33 + lane];
                    v += (val - v)*decay;
                    bool s = v >= 1.f;
                    uint32_t m = __ballot_sync(0xffffffffu, s);
                    if (s) v = 0.f;
                    if (lane == 0)
                        mdst[(((size_t)((t*16 + b)*8 + hh)*256 + n))*2 + gsel] = m;
                }
            }
        } else if (EP == 2){
            float decay = sigmoidf_(lw[7]);
#pragma unroll
            for (int k2 = 0; k2 < 4; k2++){
                int idx = k2*256 + tid;
                int j = idx >> 5, c = idx & 31;
                int col = col0 + c;
                float bvv = bias[col];
                int rb = bm + 4*j;
                float v = 0.f;
#pragma unroll
                for (int t = 0; t < 4; t++){
                    float val = es[(4*j + t)*33 + c] + bvv;
                    v += (val - v)*decay;
                    bool s = v >= 1.f;
                    anyep2 |= s;
                    h4[(size_t)(rb + t)*N + col] = s ? (uint8_t)FP8_ONE : (uint8_t)0;
                    if (s) v = 0.f;
                }
            }
        } else { // EP == 3
            int u = tid >> 1, half = tid & 1;
            int t = u >> 5, c = u & 31;
            int col = col0 + c;
            int tokb = bm >> 2;
            int b = tokb >> 8, n00 = (tokb & 255) + half*16;
            float* op = out + (((size_t)(t*16 + b)*512 + col)*256 + n00);
#pragma unroll
            for (int q4 = 0; q4 < 4; q4++){
                float4 vv;
                vv.x = es[(4*(half*16 + q4*4 + 0) + t)*33 + c];
                vv.y = es[(4*(half*16 + q4*4 + 1) + t)*33 + c];
                vv.z = es[(4*(half*16 + q4*4 + 2) + t)*33 + c];
                vv.w = es[(4*(half*16 + q4*4 + 3) + t)*33 + c];
                *(float4*)(op + q4*4) = vv;
            }
        }
    }
    if (EP == 2){
        uint32_t m = __ballot_sync(0xffffffffu, anyep2);
        if (lane == 0 && m) atomicOr(&outflag[blockIdx.y], 1u);
    }
}

// ---------------- kv = k^T v from bit masks ----------------
__global__ void __launch_bounds__(256) k_kv(const uint32_t* __restrict__ km,
                                            const uint32_t* __restrict__ vm,
                                            float* __restrict__ kvout){
    __shared__ uint32_t mk[256][2], mv[256][2];
    __shared__ uint32_t kb[64][8], vb[64][8];
    int tbh = blockIdx.x;
    int tid = threadIdx.x, lane = tid & 31, w = tid >> 5;
    uint2 a = ((const uint2*)km)[(size_t)tbh*256 + tid];
    uint2 c = ((const uint2*)vm)[(size_t)tbh*256 + tid];
    mk[tid][0] = a.x; mk[tid][1] = a.y;
    mv[tid][0] = c.x; mv[tid][1] = c.y;
    __syncthreads();
    uint32_t k0 = mk[w*32+lane][0], k1 = mk[w*32+lane][1];
    uint32_t v0 = mv[w*32+lane][0], v1 = mv[w*32+lane][1];
#pragma unroll
    for (int db = 0; db < 32; db++){
        uint32_t m;
        m = __ballot_sync(0xffffffffu, (k0 >> db) & 1); if (lane == 0) kb[db][w] = m;
        m = __ballot_sync(0xffffffffu, (k1 >> db) & 1); if (lane == 0) kb[32+db][w] = m;
        m = __ballot_sync(0xffffffffu, (v0 >> db) & 1); if (lane == 0) vb[db][w] = m;
        m = __ballot_sync(0xffffffffu, (v1 >> db) & 1); if (lane == 0) vb[32+db][w] = m;
    }
    __syncthreads();
    for (int o = tid; o < DH*DH; o += 256){
        int d = o >> 6, e = o & 63;
        int cnt = 0;
#pragma unroll
        for (int g = 0; g < 8; g++) cnt += __popc(kb[d][g] & vb[e][g]);
        kvout[(size_t)tbh*DH*DH + o] = (float)cnt;
    }
}

// ---------------- attention a = q@kv*scale + LIF -> e4m3 spikes (+flags) ----------------
__global__ void __launch_bounds__(256) k_attn_lif(const uint32_t* __restrict__ qm,
                                                  const float* __restrict__ kvin,
                                                  const float* __restrict__ lw,
                                                  uint8_t* __restrict__ h,
                                                  uint32_t* __restrict__ flag){
    __shared__ float skv[64][17];
    int bx = blockIdx.x;               // b*8 + h
    int b = bx >> 3, hh = bx & 7;
    int n = threadIdx.x;
    int lane = n & 31;
    uint32_t mq[4][2];
#pragma unroll
    for (int t = 0; t < 4; t++){
        uint2 a = ((const uint2*)qm)[(size_t)((t*16+b)*8+hh)*256 + n];
        mq[t][0] = a.x; mq[t][1] = a.y;
    }
    float decay = sigmoidf_(lw[5]);
    size_t hbase = ((size_t)(b*256 + n)*4)*512 + hh*64;
    bool any = false;
    for (int eg = 0; eg < 4; eg++){
        float v[16];
#pragma unroll
        for (int e = 0; e < 16; e++) v[e] = 0.f;
        for (int t = 0; t < 4; t++){
            int tbh = (t*16 + b)*8 + hh;
            __syncthreads();
            { int d = n >> 2, io = (n & 3)*4;
              float4 f = *(const float4*)&kvin[(size_t)tbh*4096 + d*64 + eg*16 + io];
              skv[d][io] = f.x; skv[d][io+1] = f.y; skv[d][io+2] = f.z; skv[d][io+3] = f.w; }
            __syncthreads();
            float acc[16];
#pragma unroll
            for (int e = 0; e < 16; e++) acc[e] = 0.f;
#pragma unroll
            for (int g = 0; g < 2; g++){
                uint32_t m = mq[t][g];
                for (int db = 0; db < 32; db++){
                    if ((m >> db) & 1){
                        int d = g*32 + db;
#pragma unroll
                        for (int e = 0; e < 16; e++) acc[e] += skv[d][e];
                    }
                }
            }
            uint32_t pw[4];
#pragma unroll
            for (int qq = 0; qq < 4; qq++){
                uint32_t wv = 0;
#pragma unroll
                for (int e2 = 0; e2 < 4; e2++){
                    int e = qq*4 + e2;
                    float a0 = acc[e]*0.125f;
                    v[e] += (a0 - v[e])*decay;
                    bool s = v[e] >= 1.f;
                    any |= s;
                    wv |= (s ? FP8_ONE : 0u) << (e2*8);
                    if (s) v[e] = 0.f;
                }
                pw[qq] = wv;
            }
            *(uint4*)(h + hbase + (size_t)t*512 + eg*16) = make_uint4(pw[0],pw[1],pw[2],pw[3]);
        }
    }
    uint32_t m = __ballot_sync(0xffffffffu, any);
    if (lane == 0 && m) atomicOr(&flag[(b*256 + n) >> 5], 1u);
}

// ---------------- launch ----------------
extern "C" void kernel_launch(void* const* d_in, const int* in_sizes, int n_in,
                              void* d_out, int out_size){
    const float* x      = (const float*)d_in[0];
    const float* conv_w = (const float*)d_in[1];
    const float* conv_b = (const float*)d_in[2];
    const float* ln1_g  = (const float*)d_in[3];
    const float* ln1_b  = (const float*)d_in[4];
    const float* qkv_w  = (const float*)d_in[5];
    const float* proj_w = (const float*)d_in[6];
    const float* proj_b = (const float*)d_in[7];
    const float* ln2_g  = (const float*)d_in[8];
    const float* ln2_b  = (const float*)d_in[9];
    const float* fc1_w  = (const float*)d_in[10];
    const float* fc1_b  = (const float*)d_in[11];
    const float* fc2_w  = (const float*)d_in[12];
    const float* fc2_b  = (const float*)d_in[13];
    const float* lif_w  = (const float*)d_in[14];
    float* out = (float*)d_out;

    void *p_xt, *p_y, *p_kv, *p_h, *p_h4, *p_qm, *p_km, *p_vm,
         *p_wq, *p_wp, *p_w1, *p_w2, *p_f1, *p_fa, *p_f3, *p_f4;
    cudaGetSymbolAddress(&p_xt, g_xt);
    cudaGetSymbolAddress(&p_y,  g_y);
    cudaGetSymbolAddress(&p_kv, g_kv);
    cudaGetSymbolAddress(&p_h,  g_h);
    cudaGetSymbolAddress(&p_h4, g_h4);
    cudaGetSymbolAddress(&p_qm, g_qm);
    cudaGetSymbolAddress(&p_km, g_km);
    cudaGetSymbolAddress(&p_vm, g_vm);
    cudaGetSymbolAddress(&p_wq, g_wq);
    cudaGetSymbolAddress(&p_wp, g_wp);
    cudaGetSymbolAddress(&p_w1, g_w1);
    cudaGetSymbolAddress(&p_w2, g_w2);
    cudaGetSymbolAddress(&p_f1, g_fh1);
    cudaGetSymbolAddress(&p_fa, g_fha);
    cudaGetSymbolAddress(&p_f3, g_fh3);
    cudaGetSymbolAddress(&p_f4, g_f4);

    float* xt = (float*)p_xt;
    float* y  = (float*)p_y;
    float* kv = (float*)p_kv;
    uint8_t* h  = (uint8_t*)p_h;
    uint8_t* h4 = (uint8_t*)p_h4;
    uint32_t* qm = (uint32_t*)p_qm;
    uint32_t* km = (uint32_t*)p_km;
    uint32_t* vm = (uint32_t*)p_vm;
    uint8_t* wq = (uint8_t*)p_wq;
    uint8_t* wp = (uint8_t*)p_wp;
    uint8_t* w1 = (uint8_t*)p_w1;
    uint8_t* w2 = (uint8_t*)p_w2;
    uint32_t* f1 = (uint32_t*)p_f1;
    uint32_t* fa = (uint32_t*)p_fa;
    uint32_t* f3 = (uint32_t*)p_f3;
    uint32_t* f4 = (uint32_t*)p_f4;

    cudaFuncSetAttribute((const void*)k_gemm<0,512>,  cudaFuncAttributeMaxDynamicSharedMemorySize, GEMM_DSMEM);
    cudaFuncSetAttribute((const void*)k_gemm<1,512>,  cudaFuncAttributeMaxDynamicSharedMemorySize, GEMM_DSMEM);
    cudaFuncSetAttribute((const void*)k_gemm<2,512>,  cudaFuncAttributeMaxDynamicSharedMemorySize, GEMM_DSMEM);
    cudaFuncSetAttribute((const void*)k_gemm<3,2048>, cudaFuncAttributeMaxDynamicSharedMemorySize, GEMM_DSMEM);

    // 1) weights -> e4m3 (+flag clear)
    k_cvt_all<<<3072, 256>>>(qkv_w, proj_w, fc1_w, fc2_w, wq, wp, w1, w2, f1, fa, f3, f4);
    // 2) fused LIF(x) + conv + residual -> y
    k_lifconv<<<BB*CC, 256>>>(x, lif_w, conv_w, conv_b, y);
    // 3) transpose -> xt rows (bn*4+t)
    k_tr<<<dim3(4, 8, 64), 256>>>(y, xt);
    // 4) LN1 + LIF -> h (+f1)
    k_ln_lif<<<BNROWS, 128>>>(xt, ln1_g, ln1_b, lif_w, 1, h, f1);
    // 5) QKV GEMM + LIF -> bit masks
    k_gemm<0,512><<<dim3(24, 128), 256, GEMM_DSMEM>>>(h, wq, 3*CC, lif_w, nullptr,
                                                  nullptr, nullptr, qm, km, vm, nullptr, f1, nullptr);
    // 6) kv = k^T v
    k_kv<<<TT*BB*NHEAD, 256>>>(km, vm, kv);
    // 7) a = q@kv*scale + LIF -> h (+fa)
    k_attn_lif<<<BB*NHEAD, 256>>>(qm, kv, lif_w, h, fa);
    // 8) proj GEMM: xt += h@Wp^T + proj_b (skips zero blocks)
    k_gemm<1,512><<<dim3(8, 128), 256, GEMM_DSMEM>>>(h, wp, CC, lif_w, proj_b,
                                                 xt, nullptr, nullptr, nullptr, nullptr, nullptr, fa, nullptr);
    // 9) LN2 + LIF -> h (+f3)
    k_ln_lif<<<BNROWS, 128>>>(xt, ln2_g, ln2_b, lif_w, 6, h, f3);
    // 10) FC1 GEMM + bias + LIF -> h4 (+f4)
    k_gemm<2,512><<<dim3(32, 128), 256, GEMM_DSMEM>>>(h, w1, HID, lif_w, fc1_b,
                                                  nullptr, nullptr, nullptr, nullptr, nullptr, h4, f3, f4);
    // 11) FC2 GEMM + bias + residual, transposed -> out (skips zero blocks)
    k_gemm<3,2048><<<dim3(8, 128), 256, GEMM_DSMEM>>>(h4, w2, CC, lif_w, fc2_b,
                                                 xt, out, nullptr, nullptr, nullptr, nullptr, f4, nullptr);
}

// round 16
// speedup vs baseline: 1.1305x; 1.1305x over previous
#include <cuda_runtime.h>
#include <cuda_bf16.h>
#include <cuda_fp8.h>
#include <cstdint>

// ---------------- Problem constants ----------------
#define TT 4
#define BB 16
#define CC 512
#define NN 256
#define NHEAD 8
#define DH 64
#define HID 2048
#define MROWS (TT*BB*NN)  // 16384
#define BNROWS (BB*NN)    // 4096
#define PLANE (BB*CC*NN)  // 2097152

// Row ordering for token-major tensors: r = bn*4 + t

// ---------------- Static device scratch ----------------
__device__ float          g_xt [(size_t)MROWS*CC];
__device__ float          g_y  [(size_t)TT*PLANE];
__device__ unsigned char  g_h  [(size_t)MROWS*CC];    // e4m3 spikes
__device__ unsigned char  g_h4 [(size_t)MROWS*HID];   // e4m3 spikes
__device__ uint32_t       g_qm [(size_t)TT*BB*NHEAD*NN*2];
__device__ uint32_t       g_km [(size_t)TT*BB*NHEAD*NN*2];
__device__ uint32_t       g_vm [(size_t)TT*BB*NHEAD*NN*2];
__device__ unsigned char  g_wq [(size_t)3*CC*CC];     // e4m3 weights
__device__ unsigned char  g_wp [(size_t)CC*CC];
__device__ unsigned char  g_w1 [(size_t)HID*CC];
__device__ unsigned char  g_w2 [(size_t)CC*HID];
// per-128-row-block nonzero flags for GEMM LHS skip
__device__ uint32_t       g_fh1[128];
__device__ uint32_t       g_fha[128];
__device__ uint32_t       g_fh3[128];
__device__ uint32_t       g_f4 [128];

__device__ __forceinline__ float sigmoidf_(float w){ return 1.f/(1.f+expf(-w)); }
__device__ __forceinline__ uint32_t smem_u32(const void* p){
    uint32_t a;
    asm("{ .reg .u64 t; cvta.to.shared.u64 t, %1; cvt.u32.u64 %0, t; }" : "=r"(a) : "l"(p));
    return a;
}
__device__ __forceinline__ uint32_t f2e4(float f){
    return (uint32_t)__nv_cvt_float_to_fp8(f, __NV_SATFINITE, __NV_E4M3);
}
#define FP8_ONE 0x38u

// ---------------- all weights -> e4m3 (+flag clear), one kernel ----------------
__global__ void k_cvt_all(const float* __restrict__ a0, const float* __restrict__ a1,
                          const float* __restrict__ a2, const float* __restrict__ a3,
                          uint8_t* __restrict__ d0, uint8_t* __restrict__ d1,
                          uint8_t* __restrict__ d2, uint8_t* __restrict__ d3,
                          uint32_t* f1, uint32_t* f2, uint32_t* f3, uint32_t* f4){
    if (blockIdx.x == 0 && threadIdx.x < 128){
        int i = threadIdx.x;
        f1[i] = 0; f2[i] = 0; f3[i] = 0; f4[i] = 0;
    }
    int i = blockIdx.x*blockDim.x + threadIdx.x;   // float4 index
    const int n0 = 196608, n1 = 65536, n2 = 262144, n3 = 262144;
    const float* s; uint8_t* d; int off;
    if      (i < n0){            s=a0; d=d0; off=i; }
    else if (i < n0+n1){         s=a1; d=d1; off=i-n0; }
    else if (i < n0+n1+n2){      s=a2; d=d2; off=i-n0-n1; }
    else if (i < n0+n1+n2+n3){   s=a3; d=d3; off=i-n0-n1-n2; }
    else return;
    float4 v = ((const float4*)s)[off];
    uint32_t w = f2e4(v.x) | (f2e4(v.y)<<8) | (f2e4(v.z)<<16) | (f2e4(v.w)<<24);
    ((uint32_t*)d)[off] = w;
}

// ---------------- fused LIF(x) + depthwise 3x3 conv + residual ----------------
__global__ void __launch_bounds__(256) k_lifconv(
        const float* __restrict__ x, const float* __restrict__ lw,
        const float* __restrict__ cw, const float* __restrict__ cb,
        float* __restrict__ y){
    __shared__ unsigned char sp[4][256];
    int b = blockIdx.x >> 9, c = blockIdx.x & 511;
    int px = threadIdx.x;
    size_t base = ((size_t)b*512 + c)*256 + px;
    float decay = sigmoidf_(lw[0]);
    float xv[4];
#pragma unroll
    for (int t = 0; t < 4; t++) xv[t] = x[(size_t)t*PLANE + base];
    float v = 0.f;
#pragma unroll
    for (int t = 0; t < 4; t++){
        v += (xv[t] - v)*decay;
        unsigned char s = (v >= 1.f);
        sp[t][px] = s;
        if (s) v = 0.f;
    }
    __syncthreads();
    float wk[9];
#pragma unroll
    for (int j = 0; j < 9; j++) wk[j] = cw[c*9 + j];
    float bias = cb[c];
    int h = px >> 4, w = px & 15;
#pragma unroll
    for (int t = 0; t < 4; t++){
        float acc = bias;
#pragma unroll
        for (int dy = -1; dy <= 1; dy++){
            int hh = h + dy; if ((unsigned)hh >= 16u) continue;
#pragma unroll
            for (int dx = -1; dx <= 1; dx++){
                int ww = w + dx; if ((unsigned)ww >= 16u) continue;
                acc += wk[(dy+1)*3 + (dx+1)] * (float)sp[t][hh*16 + ww];
            }
        }
        y[(size_t)t*PLANE + base] = xv[t] + acc;
    }
}

// ---------------- transpose [tb][C][N] -> xt rows (bn*4+t) ----------------
__global__ void __launch_bounds__(256) k_tr(const float* __restrict__ y, float* __restrict__ xt){
    __shared__ float s[64][65];
    int bz = blockIdx.z;                 // t*16+b
    int t = bz >> 4, b = bz & 15;
    int n0 = blockIdx.x*64, c0 = blockIdx.y*64;
    int tid = threadIdx.x;
    const float* src = y + (size_t)bz*512*256;
#pragma unroll
    for (int it = 0; it < 4; it++){
        int cr = it*16 + (tid >> 4), ng = (tid & 15)*4;
        float4 f = *(const float4*)&src[(size_t)(c0+cr)*256 + n0 + ng];
        s[cr][ng+0] = f.x; s[cr][ng+1] = f.y; s[cr][ng+2] = f.z; s[cr][ng+3] = f.w;
    }
    __syncthreads();
#pragma unroll
    for (int it = 0; it < 4; it++){
        int nr = it*16 + (tid >> 4), cg = (tid & 15)*4;
        size_t row = (size_t)(b*256 + n0 + nr)*4 + t;
        float4 f = make_float4(s[cg][nr], s[cg+1][nr], s[cg+2][nr], s[cg+3][nr]);
        *(float4*)&xt[row*512 + c0 + cg] = f;
    }
}

// ---------------- LayerNorm(C) + LIF over T -> e4m3 spikes (+flags), 1 sync ----------------
__global__ void __launch_bounds__(128) k_ln_lif(
        const float* __restrict__ xt, const float* __restrict__ g, const float* __restrict__ bv,
        const float* __restrict__ lw, int lwi, uint8_t* __restrict__ h,
        uint32_t* __restrict__ flag){
    int bn = blockIdx.x, tid = threadIdx.x;
    int lane = tid & 31, w = tid >> 5;
    __shared__ float sred[4][8];         // [warp][4 sums + 4 sumsq]
    float decay = sigmoidf_(lw[lwi]);
    float4 gg = *(const float4*)&g[tid*4];
    float4 bb = *(const float4*)&bv[tid*4];
    float4 xv[4];
    float sm[4], sq[4];
#pragma unroll
    for (int t = 0; t < 4; t++){
        xv[t] = *(const float4*)&xt[((size_t)bn*4 + t)*512 + tid*4];
        sm[t] = xv[t].x + xv[t].y + xv[t].z + xv[t].w;
        sq[t] = xv[t].x*xv[t].x + xv[t].y*xv[t].y + xv[t].z*xv[t].z + xv[t].w*xv[t].w;
    }
#pragma unroll
    for (int o = 16; o > 0; o >>= 1){
#pragma unroll
        for (int t = 0; t < 4; t++){
            sm[t] += __shfl_xor_sync(0xffffffffu, sm[t], o);
            sq[t] += __shfl_xor_sync(0xffffffffu, sq[t], o);
        }
    }
    if (lane < 8) sred[w][lane] = (lane < 4) ? sm[lane] : sq[lane-4];
    __syncthreads();
    float v0=0,v1=0,v2=0,v3=0;
    bool any = false;
#pragma unroll
    for (int t = 0; t < 4; t++){
        float ts = sred[0][t] + sred[1][t] + sred[2][t] + sred[3][t];
        float tq = sred[0][t+4] + sred[1][t+4] + sred[2][t+4] + sred[3][t+4];
        float mean = ts*(1.f/512.f);
        float var  = tq*(1.f/512.f) - mean*mean;
        float rstd = rsqrtf(var + 1e-5f);
        float4 xw = xv[t];
        float y0 = (xw.x-mean)*rstd*gg.x + bb.x;
        float y1 = (xw.y-mean)*rstd*gg.y + bb.y;
        float y2 = (xw.z-mean)*rstd*gg.z + bb.z;
        float y3 = (xw.w-mean)*rstd*gg.w + bb.w;
        v0 += (y0-v0)*decay; v1 += (y1-v1)*decay; v2 += (y2-v2)*decay; v3 += (y3-v3)*decay;
        bool s0 = v0>=1.f, s1 = v1>=1.f, s2 = v2>=1.f, s3 = v3>=1.f;
        any |= (s0|s1|s2|s3);
        uint32_t pw = (s0?FP8_ONE:0u) | ((s1?FP8_ONE:0u)<<8)
                    | ((s2?FP8_ONE:0u)<<16) | ((s3?FP8_ONE:0u)<<24);
        ((uint32_t*)(h + ((size_t)bn*4 + t)*512))[tid] = pw;
        if (s0) v0=0.f; if (s1) v1=0.f; if (s2) v2=0.f; if (s3) v3=0.f;
    }
    uint32_t m = __ballot_sync(0xffffffffu, any);
    if (lane == 0 && m) atomicOr(&flag[bn >> 5], 1u);
}

// ---------------- FP8 GEMM, tile 128x64, templated K, 4-stage, 3 CTAs/SM (R13 config) ----------------
#define BMT 128
#define BNT 64
#define BKB 64
#define STG 4
#define ROWB 80
#define STAGE_BYTES ((BMT+BNT)*ROWB)    // 15360
#define GEMM_DSMEM (STG*STAGE_BYTES)    // 61440

template<int EP, int K>
__global__ void __launch_bounds__(256, 3) k_gemm(
        const uint8_t* __restrict__ A, const uint8_t* __restrict__ W,
        int N,
        const float* __restrict__ lw, const float* __restrict__ bias,
        float* __restrict__ xt, float* __restrict__ out,
        uint32_t* __restrict__ qm, uint32_t* __restrict__ km, uint32_t* __restrict__ vm,
        uint8_t* __restrict__ h4,
        const uint32_t* __restrict__ nzf, uint32_t* __restrict__ outflag){
    extern __shared__ char dsm[];
    const int tid  = threadIdx.x;
    const int lane = tid & 31, warp = tid >> 5;
    const int wm = warp >> 1, wn = warp & 1;      // 4m x 2n warps; warp tile 32x32
    const int bm = blockIdx.y*BMT, bn = blockIdx.x*BNT;
    const uint32_t sbase = smem_u32(dsm);
    constexpr int nk = K >> 6;

    float acc[2][4][4];
#pragma unroll
    for (int i = 0; i < 2; i++)
#pragma unroll
        for (int j = 0; j < 4; j++)
#pragma unroll
            for (int r = 0; r < 4; r++) acc[i][j][r] = 0.f;

    const bool live = (nzf == nullptr) || (nzf[blockIdx.y] != 0);

    if (live){
        // hoisted per-thread copy addressing
        const int crow = tid >> 2, ccol = (tid & 3)*16;
        const uint8_t* gA0 = A + (size_t)(bm + crow)*K + ccol;
        const uint8_t* gA1 = gA0 + (size_t)64*K;
        const uint8_t* gB  = W + (size_t)(bn + crow)*K + ccol;
        const uint32_t dA0 = sbase + (uint32_t)(crow*ROWB + ccol);
        const uint32_t dA1 = dA0 + 64*ROWB;
        const uint32_t dB  = sbase + (uint32_t)(BMT*ROWB + crow*ROWB + ccol);

        auto load_stage = [&](int j){
            uint32_t so = (uint32_t)(j & (STG-1))*STAGE_BYTES;
            const uint8_t* p0 = gA0 + j*BKB;
            const uint8_t* p1 = gA1 + j*BKB;
            const uint8_t* pb = gB  + j*BKB;
            asm volatile("cp.async.cg.shared.global [%0], [%1], 16;" :: "r"(dA0+so), "l"(p0));
            asm volatile("cp.async.cg.shared.global [%0], [%1], 16;" :: "r"(dA1+so), "l"(p1));
            asm volatile("cp.async.cg.shared.global [%0], [%1], 16;" :: "r"(dB +so), "l"(pb));
            asm volatile("cp.async.commit_group;");
        };

        // hoisted fragment smem offsets
        uint32_t aoff[2], boff[2];
#pragma unroll
        for (int mt = 0; mt < 2; mt++)
            aoff[mt] = (uint32_t)((wm*32 + mt*16 + (lane & 15))*ROWB + ((lane >> 4) << 4));
#pragma unroll
        for (int ng = 0; ng < 2; ng++)
            boff[ng] = (uint32_t)(BMT*ROWB +
                       (wn*32 + ng*16 + (lane & 7) + (((lane >> 4) & 1) << 3))*ROWB +
                       (((lane >> 3) & 1) << 4));

        load_stage(0);
        load_stage(1);
        load_stage(2);

#pragma unroll 2
        for (int j = 0; j < nk; j++){
            asm volatile("cp.async.wait_group 2;");
            __syncthreads();
            uint32_t so = sbase + (uint32_t)(j & (STG-1))*STAGE_BYTES;
#pragma unroll
            for (int ks = 0; ks < 2; ks++){
                uint32_t a[2][4], b[2][4];
#pragma unroll
                for (int mt = 0; mt < 2; mt++){
                    uint32_t ad = so + aoff[mt] + ks*32;
                    asm volatile("ldmatrix.sync.aligned.m8n8.x4.shared.b16 {%0,%1,%2,%3}, [%4];"
                                 : "=r"(a[mt][0]), "=r"(a[mt][1]), "=r"(a[mt][2]), "=r"(a[mt][3])
                                 : "r"(ad));
                }
#pragma unroll
                for (int ng = 0; ng < 2; ng++){
                    uint32_t bd = so + boff[ng] + ks*32;
                    asm volatile("ldmatrix.sync.aligned.m8n8.x4.shared.b16 {%0,%1,%2,%3}, [%4];"
                                 : "=r"(b[ng][0]), "=r"(b[ng][1]), "=r"(b[ng][2]), "=r"(b[ng][3])
                                 : "r"(bd));
                }
#pragma unroll
                for (int mt = 0; mt < 2; mt++)
#pragma unroll
                    for (int nf = 0; nf < 4; nf++){
                        uint32_t b0 = b[nf >> 1][(nf & 1)*2];
                        uint32_t b1 = b[nf >> 1][(nf & 1)*2 + 1];
                        asm volatile(
                            "mma.sync.aligned.m16n8k32.row.col.f32.e4m3.e4m3.f32 "
                            "{%0,%1,%2,%3}, {%4,%5,%6,%7}, {%8,%9}, {%0,%1,%2,%3};"
                            : "+f"(acc[mt][nf][0]), "+f"(acc[mt][nf][1]),
                              "+f"(acc[mt][nf][2]), "+f"(acc[mt][nf][3])
                            : "r"(a[mt][0]), "r"(a[mt][1]), "r"(a[mt][2]), "r"(a[mt][3]),
                              "r"(b0), "r"(b1));
                    }
            }
            if (j + 3 < nk) load_stage(j + 3);
            else            asm volatile("cp.async.commit_group;");
        }
        asm volatile("cp.async.wait_group 0;");
    }

    // ================= epilogues =================
    if (EP == 1){
#pragma unroll
        for (int mt = 0; mt < 2; mt++){
            int r0 = bm + wm*32 + mt*16 + (lane >> 2);
#pragma unroll
            for (int nf = 0; nf < 4; nf++){
                int col = bn + wn*32 + nf*8 + (lane & 3)*2;
                float2 bb = *(const float2*)&bias[col];
                float2* p0 = (float2*)&xt[(size_t)r0*512 + col];
                float2 q0 = *p0;
                q0.x += acc[mt][nf][0] + bb.x; q0.y += acc[mt][nf][1] + bb.y;
                *p0 = q0;
                float2* p1 = (float2*)&xt[(size_t)(r0+8)*512 + col];
                float2 q1 = *p1;
                q1.x += acc[mt][nf][2] + bb.x; q1.y += acc[mt][nf][3] + bb.y;
                *p1 = q1;
            }
        }
        return;
    }

    if (EP == 3){
#pragma unroll
        for (int mt = 0; mt < 2; mt++){
            int r0 = bm + wm*32 + mt*16 + (lane >> 2);
#pragma unroll
            for (int nf = 0; nf < 4; nf++){
                int col = bn + wn*32 + nf*8 + (lane & 3)*2;
                float2 bb = *(const float2*)&bias[col];
                float2 x0 = *(const float2*)&xt[(size_t)r0*512 + col];
                float2 x1 = *(const float2*)&xt[(size_t)(r0+8)*512 + col];
                acc[mt][nf][0] += x0.x + bb.x; acc[mt][nf][1] += x0.y + bb.y;
                acc[mt][nf][2] += x1.x + bb.x; acc[mt][nf][3] += x1.y + bb.y;
            }
        }
    }

    // chunked smem epilogue (EP 0, 2, 3): 2 chunks of 32 cols
    bool anyep2 = false;
    float* es = (float*)dsm;
    for (int cc = 0; cc < 2; cc++){
        __syncthreads();
        if (wn == cc){
#pragma unroll
            for (int mt = 0; mt < 2; mt++)
#pragma unroll
                for (int f = 0; f < 4; f++){
                    int lc = f*8 + (lane & 3)*2;
                    int r0 = wm*32 + mt*16 + (lane >> 2);
                    es[r0*33 + lc]     = acc[mt][f][0];
                    es[r0*33 + lc + 1] = acc[mt][f][1];
                    es[(r0+8)*33 + lc]     = acc[mt][f][2];
                    es[(r0+8)*33 + lc + 1] = acc[mt][f][3];
                }
        }
        __syncthreads();
        int col0 = bn + cc*32;
        if (EP == 0){
            int isel = col0 >> 9, hh = (col0 >> 6) & 7, gsel = (col0 >> 5) & 1;
            float decay = sigmoidf_(lw[2 + isel]);
            uint32_t* mdst = (isel == 0) ? qm : (isel == 1) ? km : vm;
#pragma unroll
            for (int k2 = 0; k2 < 4; k2++){
                int j = k2*8 + warp;
                int tok = (bm >> 2) + j;
                int b = tok >> 8, n = tok & 255;
                float v = 0.f;
#pragma unroll
                for (int t = 0; t < 4; t++){
                    float val = es[(4*j + t)*33 + lane];
                    v += (val - v)*decay;
                    bool s = v >= 1.f;
                    uint32_t m = __ballot_sync(0xffffffffu, s);
                    if (s) v = 0.f;
                    if (lane == 0)
                        mdst[(((size_t)((t*16 + b)*8 + hh)*256 + n))*2 + gsel] = m;
                }
            }
        } else if (EP == 2){
            float decay = sigmoidf_(lw[7]);
#pragma unroll
            for (int k2 = 0; k2 < 4; k2++){
                int idx = k2*256 + tid;
                int j = idx >> 5, c = idx & 31;
                int col = col0 + c;
                float bvv = bias[col];
                int rb = bm + 4*j;
                float v = 0.f;
#pragma unroll
                for (int t = 0; t < 4; t++){
                    float val = es[(4*j + t)*33 + c] + bvv;
                    v += (val - v)*decay;
                    bool s = v >= 1.f;
                    anyep2 |= s;
                    h4[(size_t)(rb + t)*N + col] = s ? (uint8_t)FP8_ONE : (uint8_t)0;
                    if (s) v = 0.f;
                }
            }
        } else { // EP == 3
            int u = tid >> 1, half = tid & 1;
            int t = u >> 5, c = u & 31;
            int col = col0 + c;
            int tokb = bm >> 2;
            int b = tokb >> 8, n00 = (tokb & 255) + half*16;
            float* op = out + (((size_t)(t*16 + b)*512 + col)*256 + n00);
#pragma unroll
            for (int q4 = 0; q4 < 4; q4++){
                float4 vv;
                vv.x = es[(4*(half*16 + q4*4 + 0) + t)*33 + c];
                vv.y = es[(4*(half*16 + q4*4 + 1) + t)*33 + c];
                vv.z = es[(4*(half*16 + q4*4 + 2) + t)*33 + c];
                vv.w = es[(4*(half*16 + q4*4 + 3) + t)*33 + c];
                *(float4*)(op + q4*4) = vv;
            }
        }
    }
    if (EP == 2){
        uint32_t m = __ballot_sync(0xffffffffu, anyep2);
        if (lane == 0 && m) atomicOr(&outflag[blockIdx.y], 1u);
    }
}

// ---------------- fused kv + attention + LIF: one block per (b,h) ----------------
__global__ void __launch_bounds__(256) k_attn_fused(
        const uint32_t* __restrict__ qm, const uint32_t* __restrict__ km,
        const uint32_t* __restrict__ vm, const float* __restrict__ lw,
        uint8_t* __restrict__ h, uint32_t* __restrict__ flag){
    __shared__ uint16_t skv[4][64][66];          // exact popcount kv per t
    __shared__ uint32_t mk[256][2], mv[256][2];
    __shared__ uint32_t kb[64][8], vb[64][8];
    int bx = blockIdx.x;               // b*8 + h
    int b = bx >> 3, hh = bx & 7;
    int n = threadIdx.x;
    int lane = n & 31, w = n >> 5;

    // ---- phase 1: kv for all 4 timesteps ----
    for (int t = 0; t < 4; t++){
        size_t mbase = (size_t)((t*16 + b)*8 + hh)*256;
        uint2 ak = ((const uint2*)km)[mbase + n];
        uint2 av = ((const uint2*)vm)[mbase + n];
        mk[n][0] = ak.x; mk[n][1] = ak.y;
        mv[n][0] = av.x; mv[n][1] = av.y;
        __syncthreads();
        uint32_t k0 = mk[w*32+lane][0], k1 = mk[w*32+lane][1];
        uint32_t v0 = mv[w*32+lane][0], v1 = mv[w*32+lane][1];
#pragma unroll
        for (int db = 0; db < 32; db++){
            uint32_t m;
            m = __ballot_sync(0xffffffffu, (k0 >> db) & 1); if (lane == 0) kb[db][w] = m;
            m = __ballot_sync(0xffffffffu, (k1 >> db) & 1); if (lane == 0) kb[32+db][w] = m;
            m = __ballot_sync(0xffffffffu, (v0 >> db) & 1); if (lane == 0) vb[db][w] = m;
            m = __ballot_sync(0xffffffffu, (v1 >> db) & 1); if (lane == 0) vb[32+db][w] = m;
        }
        __syncthreads();
        for (int o = n; o < DH*DH; o += 256){
            int d = o >> 6, e = o & 63;
            int cnt = 0;
#pragma unroll
            for (int g = 0; g < 8; g++) cnt += __popc(kb[d][g] & vb[e][g]);
            skv[t][d][e] = (uint16_t)cnt;
        }
        __syncthreads();
    }

    // ---- phase 2: a = q@kv * scale, LIF, e4m3 spikes ----
    uint32_t mq[4][2];
#pragma unroll
    for (int t = 0; t < 4; t++){
        uint2 a = ((const uint2*)qm)[(size_t)((t*16+b)*8+hh)*256 + n];
        mq[t][0] = a.x; mq[t][1] = a.y;
    }
    float decay = sigmoidf_(lw[5]);
    size_t hbase = ((size_t)(b*256 + n)*4)*512 + hh*64;
    bool any = false;
    for (int eg = 0; eg < 4; eg++){
        float v[16];
#pragma unroll
        for (int e = 0; e < 16; e++) v[e] = 0.f;
#pragma unroll
        for (int t = 0; t < 4; t++){
            int acc[16];
#pragma unroll
            for (int e = 0; e < 16; e++) acc[e] = 0;
#pragma unroll
            for (int g = 0; g < 2; g++){
                uint32_t m = mq[t][g];
                for (int db = 0; db < 32; db++){
                    if ((m >> db) & 1){
                        const uint16_t* row = &skv[t][g*32 + db][eg*16];
#pragma unroll
                        for (int e = 0; e < 16; e++) acc[e] += row[e];
                    }
                }
            }
            uint32_t pw[4];
#pragma unroll
            for (int qq = 0; qq < 4; qq++){
                uint32_t wv = 0;
#pragma unroll
                for (int e2 = 0; e2 < 4; e2++){
                    int e = qq*4 + e2;
                    float a0 = (float)acc[e]*0.125f;
                    v[e] += (a0 - v[e])*decay;
                    bool s = v[e] >= 1.f;
                    any |= s;
                    wv |= (s ? FP8_ONE : 0u) << (e2*8);
                    if (s) v[e] = 0.f;
                }
                pw[qq] = wv;
            }
            *(uint4*)(h + hbase + (size_t)t*512 + eg*16) = make_uint4(pw[0],pw[1],pw[2],pw[3]);
        }
    }
    uint32_t m = __ballot_sync(0xffffffffu, any);
    if (lane == 0 && m) atomicOr(&flag[(b*256 + n) >> 5], 1u);
}

// ---------------- launch ----------------
extern "C" void kernel_launch(void* const* d_in, const int* in_sizes, int n_in,
                              void* d_out, int out_size){
    const float* x      = (const float*)d_in[0];
    const float* conv_w = (const float*)d_in[1];
    const float* conv_b = (const float*)d_in[2];
    const float* ln1_g  = (const float*)d_in[3];
    const float* ln1_b  = (const float*)d_in[4];
    const float* qkv_w  = (const float*)d_in[5];
    const float* proj_w = (const float*)d_in[6];
    const float* proj_b = (const float*)d_in[7];
    const float* ln2_g  = (const float*)d_in[8];
    const float* ln2_b  = (const float*)d_in[9];
    const float* fc1_w  = (const float*)d_in[10];
    const float* fc1_b  = (const float*)d_in[11];
    const float* fc2_w  = (const float*)d_in[12];
    const float* fc2_b  = (const float*)d_in[13];
    const float* lif_w  = (const float*)d_in[14];
    float* out = (float*)d_out;

    void *p_xt, *p_y, *p_h, *p_h4, *p_qm, *p_km, *p_vm,
         *p_wq, *p_wp, *p_w1, *p_w2, *p_f1, *p_fa, *p_f3, *p_f4;
    cudaGetSymbolAddress(&p_xt, g_xt);
    cudaGetSymbolAddress(&p_y,  g_y);
    cudaGetSymbolAddress(&p_h,  g_h);
    cudaGetSymbolAddress(&p_h4, g_h4);
    cudaGetSymbolAddress(&p_qm, g_qm);
    cudaGetSymbolAddress(&p_km, g_km);
    cudaGetSymbolAddress(&p_vm, g_vm);
    cudaGetSymbolAddress(&p_wq, g_wq);
    cudaGetSymbolAddress(&p_wp, g_wp);
    cudaGetSymbolAddress(&p_w1, g_w1);
    cudaGetSymbolAddress(&p_w2, g_w2);
    cudaGetSymbolAddress(&p_f1, g_fh1);
    cudaGetSymbolAddress(&p_fa, g_fha);
    cudaGetSymbolAddress(&p_f3, g_fh3);
    cudaGetSymbolAddress(&p_f4, g_f4);

    float* xt = (float*)p_xt;
    float* y  = (float*)p_y;
    uint8_t* h  = (uint8_t*)p_h;
    uint8_t* h4 = (uint8_t*)p_h4;
    uint32_t* qm = (uint32_t*)p_qm;
    uint32_t* km = (uint32_t*)p_km;
    uint32_t* vm = (uint32_t*)p_vm;
    uint8_t* wq = (uint8_t*)p_wq;
    uint8_t* wp = (uint8_t*)p_wp;
    uint8_t* w1 = (uint8_t*)p_w1;
    uint8_t* w2 = (uint8_t*)p_w2;
    uint32_t* f1 = (uint32_t*)p_f1;
    uint32_t* fa = (uint32_t*)p_fa;
    uint32_t* f3 = (uint32_t*)p_f3;
    uint32_t* f4 = (uint32_t*)p_f4;

    cudaFuncSetAttribute((const void*)k_gemm<0,512>,  cudaFuncAttributeMaxDynamicSharedMemorySize, GEMM_DSMEM);
    cudaFuncSetAttribute((const void*)k_gemm<1,512>,  cudaFuncAttributeMaxDynamicSharedMemorySize, GEMM_DSMEM);
    cudaFuncSetAttribute((const void*)k_gemm<2,512>,  cudaFuncAttributeMaxDynamicSharedMemorySize, GEMM_DSMEM);
    cudaFuncSetAttribute((const void*)k_gemm<3,2048>, cudaFuncAttributeMaxDynamicSharedMemorySize, GEMM_DSMEM);

    // 1) weights -> e4m3 (+flag clear)
    k_cvt_all<<<3072, 256>>>(qkv_w, proj_w, fc1_w, fc2_w, wq, wp, w1, w2, f1, fa, f3, f4);
    // 2) fused LIF(x) + conv + residual -> y
    k_lifconv<<<BB*CC, 256>>>(x, lif_w, conv_w, conv_b, y);
    // 3) transpose -> xt rows (bn*4+t)
    k_tr<<<dim3(4, 8, 64), 256>>>(y, xt);
    // 4) LN1 + LIF -> h (+f1)
    k_ln_lif<<<BNROWS, 128>>>(xt, ln1_g, ln1_b, lif_w, 1, h, f1);
    // 5) QKV GEMM + LIF -> bit masks
    k_gemm<0,512><<<dim3(24, 128), 256, GEMM_DSMEM>>>(h, wq, 3*CC, lif_w, nullptr,
                                                  nullptr, nullptr, qm, km, vm, nullptr, f1, nullptr);
    // 6) fused kv + attention + LIF -> h (+fa)
    k_attn_fused<<<BB*NHEAD, 256>>>(qm, km, vm, lif_w, h, fa);
    // 7) proj GEMM: xt += h@Wp^T + proj_b (skips zero blocks)
    k_gemm<1,512><<<dim3(8, 128), 256, GEMM_DSMEM>>>(h, wp, CC, lif_w, proj_b,
                                                 xt, nullptr, nullptr, nullptr, nullptr, nullptr, fa, nullptr);
    // 8) LN2 + LIF -> h (+f3)
    k_ln_lif<<<BNROWS, 128>>>(xt, ln2_g, ln2_b, lif_w, 6, h, f3);
    // 9) FC1 GEMM + bias + LIF -> h4 (+f4)
    k_gemm<2,512><<<dim3(32, 128), 256, GEMM_DSMEM>>>(h, w1, HID, lif_w, fc1_b,
                                                  nullptr, nullptr, nullptr, nullptr, nullptr, h4, f3, f4);
    // 10) FC2 GEMM + bias + residual, transposed -> out (skips zero blocks)
    k_gemm<3,2048><<<dim3(8, 128), 256, GEMM_DSMEM>>>(h4, w2, CC, lif_w, fc2_b,
                                                 xt, out, nullptr, nullptr, nullptr, nullptr, f4, nullptr);
}

// round 17
// speedup vs baseline: 1.1974x; 1.0592x over previous
#include <cuda_runtime.h>
#include <cuda_bf16.h>
#include <cuda_fp8.h>
#include <cstdint>

// ---------------- Problem constants ----------------
#define TT 4
#define BB 16
#define CC 512
#define NN 256
#define NHEAD 8
#define DH 64
#define HID 2048
#define MROWS (TT*BB*NN)  // 16384
#define BNROWS (BB*NN)    // 4096
#define PLANE (BB*CC*NN)  // 2097152

// Row ordering for token-major tensors: r = bn*4 + t

// ---------------- Static device scratch ----------------
__device__ float          g_xt [(size_t)MROWS*CC];
__device__ float          g_y  [(size_t)TT*PLANE];
__device__ unsigned char  g_h  [(size_t)MROWS*CC];    // e4m3 spikes
__device__ unsigned char  g_h4 [(size_t)MROWS*HID];   // e4m3 spikes
__device__ uint32_t       g_qm [(size_t)TT*BB*NHEAD*NN*2];
__device__ uint32_t       g_km [(size_t)TT*BB*NHEAD*NN*2];
__device__ uint32_t       g_vm [(size_t)TT*BB*NHEAD*NN*2];
__device__ unsigned char  g_wq [(size_t)3*CC*CC];     // e4m3 weights
__device__ unsigned char  g_wp [(size_t)CC*CC];
__device__ unsigned char  g_w1 [(size_t)HID*CC];
__device__ unsigned char  g_w2 [(size_t)CC*HID];
// per-128-row-block nonzero flags for GEMM LHS skip
__device__ uint32_t       g_fh1[128];
__device__ uint32_t       g_fha[128];
__device__ uint32_t       g_fh3[128];
__device__ uint32_t       g_f4 [128];

__device__ __forceinline__ float sigmoidf_(float w){ return 1.f/(1.f+expf(-w)); }
__device__ __forceinline__ uint32_t smem_u32(const void* p){
    uint32_t a;
    asm("{ .reg .u64 t; cvta.to.shared.u64 t, %1; cvt.u32.u64 %0, t; }" : "=r"(a) : "l"(p));
    return a;
}
__device__ __forceinline__ uint32_t f2e4(float f){
    return (uint32_t)__nv_cvt_float_to_fp8(f, __NV_SATFINITE, __NV_E4M3);
}
#define FP8_ONE 0x38u

// ---------------- k_prep: weight cvt (+flag clear) AND fused LIF+conv ----------------
// blocks [0, 3072): weight conversion; blocks [3072, 3072+8192): lifconv
#define CVT_BLOCKS 3072
__global__ void __launch_bounds__(256) k_prep(
        const float* __restrict__ a0, const float* __restrict__ a1,
        const float* __restrict__ a2, const float* __restrict__ a3,
        uint8_t* __restrict__ d0, uint8_t* __restrict__ d1,
        uint8_t* __restrict__ d2, uint8_t* __restrict__ d3,
        uint32_t* f1, uint32_t* f2, uint32_t* f3, uint32_t* f4,
        const float* __restrict__ x, const float* __restrict__ lw,
        const float* __restrict__ cw, const float* __restrict__ cb,
        float* __restrict__ y){
    if (blockIdx.x < CVT_BLOCKS){
        if (blockIdx.x == 0 && threadIdx.x < 128){
            int i = threadIdx.x;
            f1[i] = 0; f2[i] = 0; f3[i] = 0; f4[i] = 0;
        }
        int i = blockIdx.x*blockDim.x + threadIdx.x;   // float4 index
        const int n0 = 196608, n1 = 65536, n2 = 262144, n3 = 262144;
        const float* s; uint8_t* d; int off;
        if      (i < n0){            s=a0; d=d0; off=i; }
        else if (i < n0+n1){         s=a1; d=d1; off=i-n0; }
        else if (i < n0+n1+n2){      s=a2; d=d2; off=i-n0-n1; }
        else if (i < n0+n1+n2+n3){   s=a3; d=d3; off=i-n0-n1-n2; }
        else return;
        float4 v = ((const float4*)s)[off];
        uint32_t w = f2e4(v.x) | (f2e4(v.y)<<8) | (f2e4(v.z)<<16) | (f2e4(v.w)<<24);
        ((uint32_t*)d)[off] = w;
        return;
    }
    // ---- lifconv part ----
    __shared__ unsigned char sp[4][256];
    int bi = blockIdx.x - CVT_BLOCKS;
    int b = bi >> 9, c = bi & 511;
    int px = threadIdx.x;
    size_t base = ((size_t)b*512 + c)*256 + px;
    float decay = sigmoidf_(lw[0]);
    float xv[4];
#pragma unroll
    for (int t = 0; t < 4; t++) xv[t] = x[(size_t)t*PLANE + base];
    float v = 0.f;
#pragma unroll
    for (int t = 0; t < 4; t++){
        v += (xv[t] - v)*decay;
        unsigned char s = (v >= 1.f);
        sp[t][px] = s;
        if (s) v = 0.f;
    }
    __syncthreads();
    float wk[9];
#pragma unroll
    for (int j = 0; j < 9; j++) wk[j] = cw[c*9 + j];
    float bias = cb[c];
    int h = px >> 4, w = px & 15;
#pragma unroll
    for (int t = 0; t < 4; t++){
        float acc = bias;
#pragma unroll
        for (int dy = -1; dy <= 1; dy++){
            int hh = h + dy; if ((unsigned)hh >= 16u) continue;
#pragma unroll
            for (int dx = -1; dx <= 1; dx++){
                int ww = w + dx; if ((unsigned)ww >= 16u) continue;
                acc += wk[(dy+1)*3 + (dx+1)] * (float)sp[t][hh*16 + ww];
            }
        }
        y[(size_t)t*PLANE + base] = xv[t] + acc;
    }
}

// ---------------- transpose [tb][C][N] -> xt rows (bn*4+t) ----------------
__global__ void __launch_bounds__(256) k_tr(const float* __restrict__ y, float* __restrict__ xt){
    __shared__ float s[64][65];
    int bz = blockIdx.z;                 // t*16+b
    int t = bz >> 4, b = bz & 15;
    int n0 = blockIdx.x*64, c0 = blockIdx.y*64;
    int tid = threadIdx.x;
    const float* src = y + (size_t)bz*512*256;
#pragma unroll
    for (int it = 0; it < 4; it++){
        int cr = it*16 + (tid >> 4), ng = (tid & 15)*4;
        float4 f = *(const float4*)&src[(size_t)(c0+cr)*256 + n0 + ng];
        s[cr][ng+0] = f.x; s[cr][ng+1] = f.y; s[cr][ng+2] = f.z; s[cr][ng+3] = f.w;
    }
    __syncthreads();
#pragma unroll
    for (int it = 0; it < 4; it++){
        int nr = it*16 + (tid >> 4), cg = (tid & 15)*4;
        size_t row = (size_t)(b*256 + n0 + nr)*4 + t;
        float4 f = make_float4(s[cg][nr], s[cg+1][nr], s[cg+2][nr], s[cg+3][nr]);
        *(float4*)&xt[row*512 + c0 + cg] = f;
    }
}

// ---------------- LayerNorm(C) + LIF over T -> e4m3 spikes (+flags), 1 sync ----------------
__global__ void __launch_bounds__(128) k_ln_lif(
        const float* __restrict__ xt, const float* __restrict__ g, const float* __restrict__ bv,
        const float* __restrict__ lw, int lwi, uint8_t* __restrict__ h,
        uint32_t* __restrict__ flag){
    int bn = blockIdx.x, tid = threadIdx.x;
    int lane = tid & 31, w = tid >> 5;
    __shared__ float sred[4][8];         // [warp][4 sums + 4 sumsq]
    float decay = sigmoidf_(lw[lwi]);
    float4 gg = *(const float4*)&g[tid*4];
    float4 bb = *(const float4*)&bv[tid*4];
    float4 xv[4];
    float sm[4], sq[4];
#pragma unroll
    for (int t = 0; t < 4; t++){
        xv[t] = *(const float4*)&xt[((size_t)bn*4 + t)*512 + tid*4];
        sm[t] = xv[t].x + xv[t].y + xv[t].z + xv[t].w;
        sq[t] = xv[t].x*xv[t].x + xv[t].y*xv[t].y + xv[t].z*xv[t].z + xv[t].w*xv[t].w;
    }
#pragma unroll
    for (int o = 16; o > 0; o >>= 1){
#pragma unroll
        for (int t = 0; t < 4; t++){
            sm[t] += __shfl_xor_sync(0xffffffffu, sm[t], o);
            sq[t] += __shfl_xor_sync(0xffffffffu, sq[t], o);
        }
    }
    if (lane < 8) sred[w][lane] = (lane < 4) ? sm[lane] : sq[lane-4];
    __syncthreads();
    float v0=0,v1=0,v2=0,v3=0;
    bool any = false;
#pragma unroll
    for (int t = 0; t < 4; t++){
        float ts = sred[0][t] + sred[1][t] + sred[2][t] + sred[3][t];
        float tq = sred[0][t+4] + sred[1][t+4] + sred[2][t+4] + sred[3][t+4];
        float mean = ts*(1.f/512.f);
        float var  = tq*(1.f/512.f) - mean*mean;
        float rstd = rsqrtf(var + 1e-5f);
        float4 xw = xv[t];
        float y0 = (xw.x-mean)*rstd*gg.x + bb.x;
        float y1 = (xw.y-mean)*rstd*gg.y + bb.y;
        float y2 = (xw.z-mean)*rstd*gg.z + bb.z;
        float y3 = (xw.w-mean)*rstd*gg.w + bb.w;
        v0 += (y0-v0)*decay; v1 += (y1-v1)*decay; v2 += (y2-v2)*decay; v3 += (y3-v3)*decay;
        bool s0 = v0>=1.f, s1 = v1>=1.f, s2 = v2>=1.f, s3 = v3>=1.f;
        any |= (s0|s1|s2|s3);
        uint32_t pw = (s0?FP8_ONE:0u) | ((s1?FP8_ONE:0u)<<8)
                    | ((s2?FP8_ONE:0u)<<16) | ((s3?FP8_ONE:0u)<<24);
        ((uint32_t*)(h + ((size_t)bn*4 + t)*512))[tid] = pw;
        if (s0) v0=0.f; if (s1) v1=0.f; if (s2) v2=0.f; if (s3) v3=0.f;
    }
    uint32_t m = __ballot_sync(0xffffffffu, any);
    if (lane == 0 && m) atomicOr(&flag[bn >> 5], 1u);
}

// ---------------- FP8 GEMM, tile 128x64, 4-stage, 3 CTAs/SM, loads-first, full unroll ----------------
#define BMT 128
#define BNT 64
#define BKB 64
#define STG 4
#define ROWB 80
#define STAGE_BYTES ((BMT+BNT)*ROWB)    // 15360
#define GEMM_DSMEM (STG*STAGE_BYTES)    // 61440

template<int EP, int K>
__global__ void __launch_bounds__(256, 3) k_gemm(
        const uint8_t* __restrict__ A, const uint8_t* __restrict__ W,
        int N,
        const float* __restrict__ lw, const float* __restrict__ bias,
        float* __restrict__ xt, float* __restrict__ out,
        uint32_t* __restrict__ qm, uint32_t* __restrict__ km, uint32_t* __restrict__ vm,
        uint8_t* __restrict__ h4,
        const uint32_t* __restrict__ nzf, uint32_t* __restrict__ outflag){
    extern __shared__ char dsm[];
    const int tid  = threadIdx.x;
    const int lane = tid & 31, warp = tid >> 5;
    const int wm = warp >> 1, wn = warp & 1;      // 4m x 2n warps; warp tile 32x32
    const int bm = blockIdx.y*BMT, bn = blockIdx.x*BNT;
    const uint32_t sbase = smem_u32(dsm);
    constexpr int nk = K >> 6;

    float acc[2][4][4];
#pragma unroll
    for (int i = 0; i < 2; i++)
#pragma unroll
        for (int j = 0; j < 4; j++)
#pragma unroll
            for (int r = 0; r < 4; r++) acc[i][j][r] = 0.f;

    const bool live = (nzf == nullptr) || (nzf[blockIdx.y] != 0);

    if (live){
        // hoisted per-thread copy addressing
        const int crow = tid >> 2, ccol = (tid & 3)*16;
        const uint8_t* gA0 = A + (size_t)(bm + crow)*K + ccol;
        const uint8_t* gA1 = gA0 + (size_t)64*K;
        const uint8_t* gB  = W + (size_t)(bn + crow)*K + ccol;
        const uint32_t dA0 = sbase + (uint32_t)(crow*ROWB + ccol);
        const uint32_t dA1 = dA0 + 64*ROWB;
        const uint32_t dB  = sbase + (uint32_t)(BMT*ROWB + crow*ROWB + ccol);

        auto load_stage = [&](int j){
            uint32_t so = (uint32_t)(j & (STG-1))*STAGE_BYTES;
            const uint8_t* p0 = gA0 + j*BKB;
            const uint8_t* p1 = gA1 + j*BKB;
            const uint8_t* pb = gB  + j*BKB;
            asm volatile("cp.async.cg.shared.global [%0], [%1], 16;" :: "r"(dA0+so), "l"(p0));
            asm volatile("cp.async.cg.shared.global [%0], [%1], 16;" :: "r"(dA1+so), "l"(p1));
            asm volatile("cp.async.cg.shared.global [%0], [%1], 16;" :: "r"(dB +so), "l"(pb));
            asm volatile("cp.async.commit_group;");
        };

        // hoisted fragment smem offsets
        uint32_t aoff[2], boff[2];
#pragma unroll
        for (int mt = 0; mt < 2; mt++)
            aoff[mt] = (uint32_t)((wm*32 + mt*16 + (lane & 15))*ROWB + ((lane >> 4) << 4));
#pragma unroll
        for (int ng = 0; ng < 2; ng++)
            boff[ng] = (uint32_t)(BMT*ROWB +
                       (wn*32 + ng*16 + (lane & 7) + (((lane >> 4) & 1) << 3))*ROWB +
                       (((lane >> 3) & 1) << 4));

        load_stage(0);
        load_stage(1);
        load_stage(2);

#pragma unroll
        for (int j = 0; j < nk; j++){
            asm volatile("cp.async.wait_group 2;");
            __syncthreads();
            // issue next loads FIRST: slot (j+3)&3 == (j-1)&3 was consumed in iter j-1
            if (j + 3 < nk) load_stage(j + 3);
            else            asm volatile("cp.async.commit_group;");
            uint32_t so = sbase + (uint32_t)(j & (STG-1))*STAGE_BYTES;
#pragma unroll
            for (int ks = 0; ks < 2; ks++){
                uint32_t a[2][4], b[2][4];
#pragma unroll
                for (int mt = 0; mt < 2; mt++){
                    uint32_t ad = so + aoff[mt] + ks*32;
                    asm volatile("ldmatrix.sync.aligned.m8n8.x4.shared.b16 {%0,%1,%2,%3}, [%4];"
                                 : "=r"(a[mt][0]), "=r"(a[mt][1]), "=r"(a[mt][2]), "=r"(a[mt][3])
                                 : "r"(ad));
                }
#pragma unroll
                for (int ng = 0; ng < 2; ng++){
                    uint32_t bd = so + boff[ng] + ks*32;
                    asm volatile("ldmatrix.sync.aligned.m8n8.x4.shared.b16 {%0,%1,%2,%3}, [%4];"
                                 : "=r"(b[ng][0]), "=r"(b[ng][1]), "=r"(b[ng][2]), "=r"(b[ng][3])
                                 : "r"(bd));
                }
#pragma unroll
                for (int mt = 0; mt < 2; mt++)
#pragma unroll
                    for (int nf = 0; nf < 4; nf++){
                        uint32_t b0 = b[nf >> 1][(nf & 1)*2];
                        uint32_t b1 = b[nf >> 1][(nf & 1)*2 + 1];
                        asm volatile(
                            "mma.sync.aligned.m16n8k32.row.col.f32.e4m3.e4m3.f32 "
                            "{%0,%1,%2,%3}, {%4,%5,%6,%7}, {%8,%9}, {%0,%1,%2,%3};"
                            : "+f"(acc[mt][nf][0]), "+f"(acc[mt][nf][1]),
                              "+f"(acc[mt][nf][2]), "+f"(acc[mt][nf][3])
                            : "r"(a[mt][0]), "r"(a[mt][1]), "r"(a[mt][2]), "r"(a[mt][3]),
                              "r"(b0), "r"(b1));
                    }
            }
        }
        asm volatile("cp.async.wait_group 0;");
    }

    // ================= epilogues =================
    if (EP == 1){
#pragma unroll
        for (int mt = 0; mt < 2; mt++){
            int r0 = bm + wm*32 + mt*16 + (lane >> 2);
#pragma unroll
            for (int nf = 0; nf < 4; nf++){
                int col = bn + wn*32 + nf*8 + (lane & 3)*2;
                float2 bb = *(const float2*)&bias[col];
                float2* p0 = (float2*)&xt[(size_t)r0*512 + col];
                float2 q0 = *p0;
                q0.x += acc[mt][nf][0] + bb.x; q0.y += acc[mt][nf][1] + bb.y;
                *p0 = q0;
                float2* p1 = (float2*)&xt[(size_t)(r0+8)*512 + col];
                float2 q1 = *p1;
                q1.x += acc[mt][nf][2] + bb.x; q1.y += acc[mt][nf][3] + bb.y;
                *p1 = q1;
            }
        }
        return;
    }

    if (EP == 3){
#pragma unroll
        for (int mt = 0; mt < 2; mt++){
            int r0 = bm + wm*32 + mt*16 + (lane >> 2);
#pragma unroll
            for (int nf = 0; nf < 4; nf++){
                int col = bn + wn*32 + nf*8 + (lane & 3)*2;
                float2 bb = *(const float2*)&bias[col];
                float2 x0 = *(const float2*)&xt[(size_t)r0*512 + col];
                float2 x1 = *(const float2*)&xt[(size_t)(r0+8)*512 + col];
                acc[mt][nf][0] += x0.x + bb.x; acc[mt][nf][1] += x0.y + bb.y;
                acc[mt][nf][2] += x1.x + bb.x; acc[mt][nf][3] += x1.y + bb.y;
            }
        }
    }

    // chunked smem epilogue (EP 0, 2, 3): 2 chunks of 32 cols
    bool anyep2 = false;
    float* es = (float*)dsm;
    for (int cc = 0; cc < 2; cc++){
        __syncthreads();
        if (wn == cc){
#pragma unroll
            for (int mt = 0; mt < 2; mt++)
#pragma unroll
                for (int f = 0; f < 4; f++){
                    int lc = f*8 + (lane & 3)*2;
                    int r0 = wm*32 + mt*16 + (lane >> 2);
                    es[r0*33 + lc]     = acc[mt][f][0];
                    es[r0*33 + lc + 1] = acc[mt][f][1];
                    es[(r0+8)*33 + lc]     = acc[mt][f][2];
                    es[(r0+8)*33 + lc + 1] = acc[mt][f][3];
                }
        }
        __syncthreads();
        int col0 = bn + cc*32;
        if (EP == 0){
            int isel = col0 >> 9, hh = (col0 >> 6) & 7, gsel = (col0 >> 5) & 1;
            float decay = sigmoidf_(lw[2 + isel]);
            uint32_t* mdst = (isel == 0) ? qm : (isel == 1) ? km : vm;
#pragma unroll
            for (int k2 = 0; k2 < 4; k2++){
                int j = k2*8 + warp;
                int tok = (bm >> 2) + j;
                int b = tok >> 8, n = tok & 255;
                float v = 0.f;
#pragma unroll
                for (int t = 0; t < 4; t++){
                    float val = es[(4*j + t)*33 + lane];
                    v += (val - v)*decay;
                    bool s = v >= 1.f;
                    uint32_t m = __ballot_sync(0xffffffffu, s);
                    if (s) v = 0.f;
                    if (lane == 0)
                        mdst[(((size_t)((t*16 + b)*8 + hh)*256 + n))*2 + gsel] = m;
                }
            }
        } else if (EP == 2){
            float decay = sigmoidf_(lw[7]);
#pragma unroll
            for (int k2 = 0; k2 < 4; k2++){
                int idx = k2*256 + tid;
                int j = idx >> 5, c = idx & 31;
                int col = col0 + c;
                float bvv = bias[col];
                int rb = bm + 4*j;
                float v = 0.f;
#pragma unroll
                for (int t = 0; t < 4; t++){
                    float val = es[(4*j + t)*33 + c] + bvv;
                    v += (val - v)*decay;
                    bool s = v >= 1.f;
                    anyep2 |= s;
                    h4[(size_t)(rb + t)*N + col] = s ? (uint8_t)FP8_ONE : (uint8_t)0;
                    if (s) v = 0.f;
                }
            }
        } else { // EP == 3
            int u = tid >> 1, half = tid & 1;
            int t = u >> 5, c = u & 31;
            int col = col0 + c;
            int tokb = bm >> 2;
            int b = tokb >> 8, n00 = (tokb & 255) + half*16;
            float* op = out + (((size_t)(t*16 + b)*512 + col)*256 + n00);
#pragma unroll
            for (int q4 = 0; q4 < 4; q4++){
                float4 vv;
                vv.x = es[(4*(half*16 + q4*4 + 0) + t)*33 + c];
                vv.y = es[(4*(half*16 + q4*4 + 1) + t)*33 + c];
                vv.z = es[(4*(half*16 + q4*4 + 2) + t)*33 + c];
                vv.w = es[(4*(half*16 + q4*4 + 3) + t)*33 + c];
                *(float4*)(op + q4*4) = vv;
            }
        }
    }
    if (EP == 2){
        uint32_t m = __ballot_sync(0xffffffffu, anyep2);
        if (lane == 0 && m) atomicOr(&outflag[blockIdx.y], 1u);
    }
}

// ---------------- fused kv + attention + LIF: one block per (b,h) ----------------
__global__ void __launch_bounds__(256) k_attn_fused(
        const uint32_t* __restrict__ qm, const uint32_t* __restrict__ km,
        const uint32_t* __restrict__ vm, const float* __restrict__ lw,
        uint8_t* __restrict__ h, uint32_t* __restrict__ flag){
    __shared__ uint16_t skv[4][64][66];          // exact popcount kv per t
    __shared__ uint32_t mk[256][2], mv[256][2];
    __shared__ uint32_t kb[64][8], vb[64][8];
    int bx = blockIdx.x;               // b*8 + h
    int b = bx >> 3, hh = bx & 7;
    int n = threadIdx.x;
    int lane = n & 31, w = n >> 5;

    // ---- phase 1: kv for all 4 timesteps ----
    for (int t = 0; t < 4; t++){
        size_t mbase = (size_t)((t*16 + b)*8 + hh)*256;
        uint2 ak = ((const uint2*)km)[mbase + n];
        uint2 av = ((const uint2*)vm)[mbase + n];
        mk[n][0] = ak.x; mk[n][1] = ak.y;
        mv[n][0] = av.x; mv[n][1] = av.y;
        __syncthreads();
        uint32_t k0 = mk[w*32+lane][0], k1 = mk[w*32+lane][1];
        uint32_t v0 = mv[w*32+lane][0], v1 = mv[w*32+lane][1];
#pragma unroll
        for (int db = 0; db < 32; db++){
            uint32_t m;
            m = __ballot_sync(0xffffffffu, (k0 >> db) & 1); if (lane == 0) kb[db][w] = m;
            m = __ballot_sync(0xffffffffu, (k1 >> db) & 1); if (lane == 0) kb[32+db][w] = m;
            m = __ballot_sync(0xffffffffu, (v0 >> db) & 1); if (lane == 0) vb[db][w] = m;
            m = __ballot_sync(0xffffffffu, (v1 >> db) & 1); if (lane == 0) vb[32+db][w] = m;
        }
        __syncthreads();
        for (int o = n; o < DH*DH; o += 256){
            int d = o >> 6, e = o & 63;
            int cnt = 0;
#pragma unroll
            for (int g = 0; g < 8; g++) cnt += __popc(kb[d][g] & vb[e][g]);
            skv[t][d][e] = (uint16_t)cnt;
        }
        __syncthreads();
    }

    // ---- phase 2: a = q@kv * scale, LIF, e4m3 spikes ----
    uint32_t mq[4][2];
#pragma unroll
    for (int t = 0; t < 4; t++){
        uint2 a = ((const uint2*)qm)[(size_t)((t*16+b)*8+hh)*256 + n];
        mq[t][0] = a.x; mq[t][1] = a.y;
    }
    float decay = sigmoidf_(lw[5]);
    size_t hbase = ((size_t)(b*256 + n)*4)*512 + hh*64;
    bool any = false;
    for (int eg = 0; eg < 4; eg++){
        float v[16];
#pragma unroll
        for (int e = 0; e < 16; e++) v[e] = 0.f;
#pragma unroll
        for (int t = 0; t < 4; t++){
            int acc[16];
#pragma unroll
            for (int e = 0; e < 16; e++) acc[e] = 0;
#pragma unroll
            for (int g = 0; g < 2; g++){
                uint32_t m = mq[t][g];
                for (int db = 0; db < 32; db++){
                    if ((m >> db) & 1){
                        const uint16_t* row = &skv[t][g*32 + db][eg*16];
#pragma unroll
                        for (int e = 0; e < 16; e++) acc[e] += row[e];
                    }
                }
            }
            uint32_t pw[4];
#pragma unroll
            for (int qq = 0; qq < 4; qq++){
                uint32_t wv = 0;
#pragma unroll
                for (int e2 = 0; e2 < 4; e2++){
                    int e = qq*4 + e2;
                    float a0 = (float)acc[e]*0.125f;
                    v[e] += (a0 - v[e])*decay;
                    bool s = v[e] >= 1.f;
                    any |= s;
                    wv |= (s ? FP8_ONE : 0u) << (e2*8);
                    if (s) v[e] = 0.f;
                }
                pw[qq] = wv;
            }
            *(uint4*)(h + hbase + (size_t)t*512 + eg*16) = make_uint4(pw[0],pw[1],pw[2],pw[3]);
        }
    }
    uint32_t m = __ballot_sync(0xffffffffu, any);
    if (lane == 0 && m) atomicOr(&flag[(b*256 + n) >> 5], 1u);
}

// ---------------- launch ----------------
extern "C" void kernel_launch(void* const* d_in, const int* in_sizes, int n_in,
                              void* d_out, int out_size){
    const float* x      = (const float*)d_in[0];
    const float* conv_w = (const float*)d_in[1];
    const float* conv_b = (const float*)d_in[2];
    const float* ln1_g  = (const float*)d_in[3];
    const float* ln1_b  = (const float*)d_in[4];
    const float* qkv_w  = (const float*)d_in[5];
    const float* proj_w = (const float*)d_in[6];
    const float* proj_b = (const float*)d_in[7];
    const float* ln2_g  = (const float*)d_in[8];
    const float* ln2_b  = (const float*)d_in[9];
    const float* fc1_w  = (const float*)d_in[10];
    const float* fc1_b  = (const float*)d_in[11];
    const float* fc2_w  = (const float*)d_in[12];
    const float* fc2_b  = (const float*)d_in[13];
    const float* lif_w  = (const float*)d_in[14];
    float* out = (float*)d_out;

    void *p_xt, *p_y, *p_h, *p_h4, *p_qm, *p_km, *p_vm,
         *p_wq, *p_wp, *p_w1, *p_w2, *p_f1, *p_fa, *p_f3, *p_f4;
    cudaGetSymbolAddress(&p_xt, g_xt);
    cudaGetSymbolAddress(&p_y,  g_y);
    cudaGetSymbolAddress(&p_h,  g_h);
    cudaGetSymbolAddress(&p_h4, g_h4);
    cudaGetSymbolAddress(&p_qm, g_qm);
    cudaGetSymbolAddress(&p_km, g_km);
    cudaGetSymbolAddress(&p_vm, g_vm);
    cudaGetSymbolAddress(&p_wq, g_wq);
    cudaGetSymbolAddress(&p_wp, g_wp);
    cudaGetSymbolAddress(&p_w1, g_w1);
    cudaGetSymbolAddress(&p_w2, g_w2);
    cudaGetSymbolAddress(&p_f1, g_fh1);
    cudaGetSymbolAddress(&p_fa, g_fha);
    cudaGetSymbolAddress(&p_f3, g_fh3);
    cudaGetSymbolAddress(&p_f4, g_f4);

    float* xt = (float*)p_xt;
    float* y  = (float*)p_y;
    uint8_t* h  = (uint8_t*)p_h;
    uint8_t* h4 = (uint8_t*)p_h4;
    uint32_t* qm = (uint32_t*)p_qm;
    uint32_t* km = (uint32_t*)p_km;
    uint32_t* vm = (uint32_t*)p_vm;
    uint8_t* wq = (uint8_t*)p_wq;
    uint8_t* wp = (uint8_t*)p_wp;
    uint8_t* w1 = (uint8_t*)p_w1;
    uint8_t* w2 = (uint8_t*)p_w2;
    uint32_t* f1 = (uint32_t*)p_f1;
    uint32_t* fa = (uint32_t*)p_fa;
    uint32_t* f3 = (uint32_t*)p_f3;
    uint32_t* f4 = (uint32_t*)p_f4;

    cudaFuncSetAttribute((const void*)k_gemm<0,512>,  cudaFuncAttributeMaxDynamicSharedMemorySize, GEMM_DSMEM);
    cudaFuncSetAttribute((const void*)k_gemm<1,512>,  cudaFuncAttributeMaxDynamicSharedMemorySize, GEMM_DSMEM);
    cudaFuncSetAttribute((const void*)k_gemm<2,512>,  cudaFuncAttributeMaxDynamicSharedMemorySize, GEMM_DSMEM);
    cudaFuncSetAttribute((const void*)k_gemm<3,2048>, cudaFuncAttributeMaxDynamicSharedMemorySize, GEMM_DSMEM);

    // 1) weights -> e4m3 + flag clear + fused LIF(x)+conv -> y (one kernel)
    k_prep<<<CVT_BLOCKS + BB*CC, 256>>>(qkv_w, proj_w, fc1_w, fc2_w, wq, wp, w1, w2,
                                        f1, fa, f3, f4, x, lif_w, conv_w, conv_b, y);
    // 2) transpose -> xt rows (bn*4+t)
    k_tr<<<dim3(4, 8, 64), 256>>>(y, xt);
    // 3) LN1 + LIF -> h (+f1)
    k_ln_lif<<<BNROWS, 128>>>(xt, ln1_g, ln1_b, lif_w, 1, h, f1);
    // 4) QKV GEMM + LIF -> bit masks
    k_gemm<0,512><<<dim3(24, 128), 256, GEMM_DSMEM>>>(h, wq, 3*CC, lif_w, nullptr,
                                                  nullptr, nullptr, qm, km, vm, nullptr, f1, nullptr);
    // 5) fused kv + attention + LIF -> h (+fa)
    k_attn_fused<<<BB*NHEAD, 256>>>(qm, km, vm, lif_w, h, fa);
    // 6) proj GEMM: xt += h@Wp^T + proj_b (skips zero blocks)
    k_gemm<1,512><<<dim3(8, 128), 256, GEMM_DSMEM>>>(h, wp, CC, lif_w, proj_b,
                                                 xt, nullptr, nullptr, nullptr, nullptr, nullptr, fa, nullptr);
    // 7) LN2 + LIF -> h (+f3)
    k_ln_lif<<<BNROWS, 128>>>(xt, ln2_g, ln2_b, lif_w, 6, h, f3);
    // 8) FC1 GEMM + bias + LIF -> h4 (+f4)
    k_gemm<2,512><<<dim3(32, 128), 256, GEMM_DSMEM>>>(h, w1, HID, lif_w, fc1_b,
                                                  nullptr, nullptr, nullptr, nullptr, nullptr, h4, f3, f4);
    // 9) FC2 GEMM + bias + residual, transposed -> out (skips zero blocks)
    k_gemm<3,2048><<<dim3(8, 128), 256, GEMM_DSMEM>>>(h4, w2, CC, lif_w, fc2_b,
                                                 xt, out, nullptr, nullptr, nullptr, nullptr, f4, nullptr);
}